// round 1
// baseline (speedup 1.0000x reference)
#include <cuda_runtime.h>
#include <cuda_bf16.h>
#include <math.h>
#include <stdint.h>

// Problem dims
#define TT    1024      // timesteps
#define HID   256       // hidden
#define FIN   40        // input features
#define NSPK  1251
#define BATCH 64

// Pipeline config
#define G      32       // CTAs per layer
#define CHUNK  8        // h-indices per CTA  (HID / G)
#define ROWS   32       // gate rows per CTA  (4 * CHUNK)
#define NCTA   (3 * G)  // total pipeline CTAs

#define CANARY_I 0x7fb0beef  // NaN payload: data-as-flag sentinel

// Scratch (device globals; no allocation allowed)
__device__ float g_hbuf[3][TT + 1][HID];   // h history per layer; [.][0] = zeros
__device__ float g_xg0[TT][G][ROWS];       // precomputed layer-0 input proj (+biases), permuted
__device__ float g_logits[TT * NSPK];

// ---------------------------------------------------------------------------
// K1: init h buffers: t==0 -> 0.0f, else canary
// ---------------------------------------------------------------------------
__global__ void init_kernel() {
    int idx = blockIdx.x * 256 + threadIdx.x;
    const int total = 3 * (TT + 1) * HID;
    if (idx < total) {
        int t = (idx / HID) % (TT + 1);
        ((float*)g_hbuf)[idx] = (t == 0) ? 0.0f : __int_as_float(CANARY_I);
    }
}

// ---------------------------------------------------------------------------
// K2: xg0[t][grow] = b_ih0[grow] + b_hh0[grow] + sum_f x[63,t,f] * w_ih0[grow,f]
// stored permuted as g_xg0[t][cta][gate*8 + jj]  (grow = gate*256 + cta*8 + jj)
// 128 blocks x 256 threads; each block does 8 timesteps; each thread 4 gate rows.
// ---------------------------------------------------------------------------
__global__ void xg0_kernel(const float* __restrict__ x,
                           const float* __restrict__ w_ih0,
                           const float* __restrict__ b_ih0,
                           const float* __restrict__ b_hh0) {
    __shared__ float xs[8][FIN];
    const int t0 = blockIdx.x * 8;
    const int tid = threadIdx.x;

    for (int i = tid; i < 8 * FIN; i += 256) {
        int tt = i / FIN, f = i % FIN;
        xs[tt][f] = x[((size_t)(BATCH - 1) * TT + (t0 + tt)) * FIN + f];
    }
    __syncthreads();

    const int cta = tid >> 3;
    const int jj  = tid & 7;

    for (int q = 0; q < 4; q++) {             // q = gate
        int grow = q * 256 + tid;
        float w[FIN];
        const float4* wr = (const float4*)(w_ih0 + (size_t)grow * FIN);
        #pragma unroll
        for (int i = 0; i < FIN / 4; i++) {
            float4 v = wr[i];
            w[4 * i] = v.x; w[4 * i + 1] = v.y; w[4 * i + 2] = v.z; w[4 * i + 3] = v.w;
        }
        float bb = b_ih0[grow] + b_hh0[grow];
        #pragma unroll
        for (int tt = 0; tt < 8; tt++) {
            float s = bb;
            #pragma unroll
            for (int f = 0; f < FIN; f++) s += w[f] * xs[tt][f];
            g_xg0[t0 + tt][cta][q * 8 + jj] = s;
        }
    }
}

// ---------------------------------------------------------------------------
// K3: persistent pipelined LSTM. 96 CTAs (3 layers x 32), 256 threads each.
// CTA (layer,cta) owns h-indices [cta*8, cta*8+8) -> 32 gate rows.
// Weights SMEM-resident as [row][ (w_ih | w_hh) ] fp32.
// Sync: NaN-canary data-as-flag polling on g_hbuf words.
// ---------------------------------------------------------------------------
__global__ void __launch_bounds__(256, 1)
lstm_pipeline(const float* __restrict__ w_hh0,
              const float* __restrict__ w_ih1, const float* __restrict__ w_hh1,
              const float* __restrict__ b_ih1, const float* __restrict__ b_hh1,
              const float* __restrict__ w_ih2, const float* __restrict__ w_hh2,
              const float* __restrict__ b_ih2, const float* __restrict__ b_hh2) {
    extern __shared__ float sm[];
    const int layer = blockIdx.x >> 5;
    const int cta   = blockIdx.x & 31;
    const int tid   = threadIdx.x;
    const int warp  = tid >> 5;
    const int lane  = tid & 31;

    float* wsm  = sm;                       // ROWS * 512 (layer0 uses 256 cols)
    float* harr = sm + ROWS * 512;          // 512
    float* gsum = harr + 512;               // 32
    float* bsm  = gsum + 32;                // 32
    float* xarr = bsm + 32;                 // 32

    const float *wih = nullptr, *whh = nullptr, *bih = nullptr, *bhh = nullptr;
    if (layer == 0)      { whh = w_hh0; }
    else if (layer == 1) { wih = w_ih1; whh = w_hh1; bih = b_ih1; bhh = b_hh1; }
    else                 { wih = w_ih2; whh = w_hh2; bih = b_ih2; bhh = b_hh2; }

    const int DLEN = (layer == 0) ? HID : 2 * HID;

    // Stage weights into SMEM (one time)
    for (int i = tid; i < ROWS * DLEN; i += 256) {
        int lr = i / DLEN;
        int k  = i - lr * DLEN;
        int grow = (lr >> 3) * HID + cta * CHUNK + (lr & 7);
        float v;
        if (layer == 0) v = whh[(size_t)grow * HID + k];
        else v = (k < HID) ? wih[(size_t)grow * HID + k]
                           : whh[(size_t)grow * HID + (k - HID)];
        wsm[lr * DLEN + k] = v;
    }
    if (tid < 32) {
        int grow = (tid >> 3) * HID + cta * CHUNK + (tid & 7);
        bsm[tid] = (layer == 0) ? 0.0f : (bih[grow] + bhh[grow]);
    }
    __syncthreads();

    float creg = 0.0f;  // cell state, valid for tid < CHUNK

    volatile float* hb_self = &g_hbuf[layer][0][0];
    volatile float* hb_in   = (layer > 0) ? &g_hbuf[layer - 1][0][0] : nullptr;

    for (int t = 0; t < TT; t++) {
        // ---- poll phase (data-as-flag) ----
        if (layer > 0) {
            volatile float* pin = hb_in + (size_t)(t + 1) * HID + tid;
            volatile float* ppr = hb_self + (size_t)t * HID + tid;
            float va = 0.f, vb = 0.f;
            int got = 0;
            do {
                if (!(got & 1)) { va = *pin; if (__float_as_int(va) != CANARY_I) got |= 1; }
                if (!(got & 2)) { vb = *ppr; if (__float_as_int(vb) != CANARY_I) got |= 2; }
            } while (got != 3);
            harr[tid] = va;          // cols [0,256): input h (w_ih part)
            harr[HID + tid] = vb;    // cols [256,512): prev h (w_hh part)
        } else {
            volatile float* ppr = hb_self + (size_t)t * HID + tid;
            float v;
            do { v = *ppr; } while (__float_as_int(v) == CANARY_I);
            harr[tid] = v;
            if (tid < 32) xarr[tid] = g_xg0[t][cta][tid];
        }
        __syncthreads();

        // ---- dot phase: warp w handles rows 4w..4w+3 ----
        float a0 = 0.f, a1 = 0.f, a2 = 0.f, a3 = 0.f;
        const int r0 = warp * 4;
        if (layer == 0) {
            const float4* hv = (const float4*)harr;
            const float4* p0 = (const float4*)(wsm + (r0 + 0) * 256);
            const float4* p1 = (const float4*)(wsm + (r0 + 1) * 256);
            const float4* p2 = (const float4*)(wsm + (r0 + 2) * 256);
            const float4* p3 = (const float4*)(wsm + (r0 + 3) * 256);
            #pragma unroll
            for (int i = 0; i < 2; i++) {
                int idx = i * 32 + lane;
                float4 h = hv[idx];
                float4 q;
                q = p0[idx]; a0 += q.x*h.x + q.y*h.y + q.z*h.z + q.w*h.w;
                q = p1[idx]; a1 += q.x*h.x + q.y*h.y + q.z*h.z + q.w*h.w;
                q = p2[idx]; a2 += q.x*h.x + q.y*h.y + q.z*h.z + q.w*h.w;
                q = p3[idx]; a3 += q.x*h.x + q.y*h.y + q.z*h.z + q.w*h.w;
            }
        } else {
            const float4* hv = (const float4*)harr;
            const float4* p0 = (const float4*)(wsm + (r0 + 0) * 512);
            const float4* p1 = (const float4*)(wsm + (r0 + 1) * 512);
            const float4* p2 = (const float4*)(wsm + (r0 + 2) * 512);
            const float4* p3 = (const float4*)(wsm + (r0 + 3) * 512);
            #pragma unroll
            for (int i = 0; i < 4; i++) {
                int idx = i * 32 + lane;
                float4 h = hv[idx];
                float4 q;
                q = p0[idx]; a0 += q.x*h.x + q.y*h.y + q.z*h.z + q.w*h.w;
                q = p1[idx]; a1 += q.x*h.x + q.y*h.y + q.z*h.z + q.w*h.w;
                q = p2[idx]; a2 += q.x*h.x + q.y*h.y + q.z*h.z + q.w*h.w;
                q = p3[idx]; a3 += q.x*h.x + q.y*h.y + q.z*h.z + q.w*h.w;
            }
        }
        #pragma unroll
        for (int off = 16; off > 0; off >>= 1) {
            a0 += __shfl_xor_sync(0xffffffffu, a0, off);
            a1 += __shfl_xor_sync(0xffffffffu, a1, off);
            a2 += __shfl_xor_sync(0xffffffffu, a2, off);
            a3 += __shfl_xor_sync(0xffffffffu, a3, off);
        }
        if (lane == 0) {
            gsum[r0 + 0] = a0; gsum[r0 + 1] = a1;
            gsum[r0 + 2] = a2; gsum[r0 + 3] = a3;
        }
        __syncthreads();

        // ---- activation (threads 0..7 own their h/c index) ----
        if (tid < CHUNK) {
            float gi = gsum[tid]      + bsm[tid];
            float gf = gsum[8 + tid]  + bsm[8 + tid];
            float gg = gsum[16 + tid] + bsm[16 + tid];
            float go = gsum[24 + tid] + bsm[24 + tid];
            if (layer == 0) {
                gi += xarr[tid];      gf += xarr[8 + tid];
                gg += xarr[16 + tid]; go += xarr[24 + tid];
            }
            float i_ = 1.0f / (1.0f + __expf(-gi));
            float f_ = 1.0f / (1.0f + __expf(-gf));
            float g_ = 1.0f - 2.0f / (__expf(2.0f * gg) + 1.0f);   // tanh
            float o_ = 1.0f / (1.0f + __expf(-go));
            creg = f_ * creg + i_ * g_;
            float th = 1.0f - 2.0f / (__expf(2.0f * creg) + 1.0f); // tanh(c)
            float h = o_ * th;
            volatile float* dst = &g_hbuf[layer][t + 1][cta * CHUNK + tid];
            *dst = h;
        }
        // next iteration's first __syncthreads orders gsum reuse; harr rewrites are
        // safe because all dot-phase reads completed before the sync above.
    }
}

// ---------------------------------------------------------------------------
// K4: classifier GEMM: logits[t][s] = h2[t] . w_lin[s] + b_lin[s]
// 128 blocks x 256 threads; block = 8 timesteps, loop over all 1251 speakers.
// ---------------------------------------------------------------------------
__global__ void classify_kernel(const float* __restrict__ wlin,
                                const float* __restrict__ blin) {
    __shared__ float hs[8][HID];
    const int t0 = blockIdx.x * 8;
    const int tid = threadIdx.x;

    for (int i = tid; i < 8 * HID; i += 256) {
        int tt = i >> 8, k = i & 255;
        hs[tt][k] = g_hbuf[2][t0 + tt + 1][k];
    }
    __syncthreads();

    for (int spk = tid; spk < NSPK; spk += 256) {
        const float4* wr = (const float4*)(wlin + (size_t)spk * HID);
        float acc[8];
        #pragma unroll
        for (int tt = 0; tt < 8; tt++) acc[tt] = 0.0f;
        #pragma unroll 8
        for (int k4 = 0; k4 < HID / 4; k4++) {
            float4 w = wr[k4];
            #pragma unroll
            for (int tt = 0; tt < 8; tt++) {
                float4 h = *(const float4*)&hs[tt][k4 << 2];
                acc[tt] += w.x * h.x + w.y * h.y + w.z * h.z + w.w * h.w;
            }
        }
        float bb = blin[spk];
        #pragma unroll
        for (int tt = 0; tt < 8; tt++) {
            g_logits[(size_t)(t0 + tt) * NSPK + spk] = acc[tt] + bb;
        }
    }
}

// ---------------------------------------------------------------------------
// K5: row-wise log_softmax over NSPK, one block per timestep.
// ---------------------------------------------------------------------------
__global__ void softmax_kernel(float* __restrict__ out) {
    const int t = blockIdx.x;
    const int tid = threadIdx.x;
    __shared__ float red[256];
    const float* row = g_logits + (size_t)t * NSPK;

    float mx = -INFINITY;
    for (int s = tid; s < NSPK; s += 256) mx = fmaxf(mx, row[s]);
    red[tid] = mx; __syncthreads();
    for (int o = 128; o > 0; o >>= 1) {
        if (tid < o) red[tid] = fmaxf(red[tid], red[tid + o]);
        __syncthreads();
    }
    mx = red[0]; __syncthreads();

    float sum = 0.0f;
    for (int s = tid; s < NSPK; s += 256) sum += expf(row[s] - mx);
    red[tid] = sum; __syncthreads();
    for (int o = 128; o > 0; o >>= 1) {
        if (tid < o) red[tid] += red[tid + o];
        __syncthreads();
    }
    float lse = mx + logf(red[0]);

    for (int s = tid; s < NSPK; s += 256) out[(size_t)t * NSPK + s] = row[s] - lse;
}

// ---------------------------------------------------------------------------
extern "C" void kernel_launch(void* const* d_in, const int* in_sizes, int n_in,
                              void* d_out, int out_size) {
    const float* x     = (const float*)d_in[0];
    const float* w_ih0 = (const float*)d_in[1];
    const float* w_hh0 = (const float*)d_in[2];
    const float* b_ih0 = (const float*)d_in[3];
    const float* b_hh0 = (const float*)d_in[4];
    const float* w_ih1 = (const float*)d_in[5];
    const float* w_hh1 = (const float*)d_in[6];
    const float* b_ih1 = (const float*)d_in[7];
    const float* b_hh1 = (const float*)d_in[8];
    const float* w_ih2 = (const float*)d_in[9];
    const float* w_hh2 = (const float*)d_in[10];
    const float* b_ih2 = (const float*)d_in[11];
    const float* b_hh2 = (const float*)d_in[12];
    const float* w_lin = (const float*)d_in[13];
    const float* b_lin = (const float*)d_in[14];
    float* out = (float*)d_out;

    const int smem_bytes = (ROWS * 512 + 512 + 32 + 32 + 32) * (int)sizeof(float);
    cudaFuncSetAttribute(lstm_pipeline,
                         cudaFuncAttributeMaxDynamicSharedMemorySize, smem_bytes);

    const int init_total = 3 * (TT + 1) * HID;
    init_kernel<<<(init_total + 255) / 256, 256>>>();
    xg0_kernel<<<TT / 8, 256>>>(x, w_ih0, b_ih0, b_hh0);
    lstm_pipeline<<<NCTA, 256, smem_bytes>>>(w_hh0,
                                             w_ih1, w_hh1, b_ih1, b_hh1,
                                             w_ih2, w_hh2, b_ih2, b_hh2);
    classify_kernel<<<TT / 8, 256>>>(w_lin, b_lin);
    softmax_kernel<<<TT, 256>>>(out);
}

// round 2
// speedup vs baseline: 1.3204x; 1.3204x over previous
#include <cuda_runtime.h>
#include <cuda_bf16.h>
#include <math.h>
#include <stdint.h>

// Problem dims
#define TT    1024
#define HID   256
#define FIN   40
#define NSPK  1251
#define BATCH 64

// Pipeline config
#define G      32       // CTAs per layer
#define CHUNK  8        // h-indices per CTA
#define ROWS   32       // gate rows per CTA
#define NCTA   (3 * G)

#define CANARY_I 0x7fb0beef

__device__ float g_hbuf[3][TT + 1][HID];
__device__ float g_xg0[TT][G][ROWS];
__device__ float g_logits[TT * NSPK];

#define FMA2(d, a, b, c) \
    asm("fma.rn.f32x2 %0, %1, %2, %3;" : "=l"(d) : "l"(a), "l"(b), "l"(c))

__device__ __forceinline__ float tanh_fast(float x) {
    float r;
    asm("tanh.approx.f32 %0, %1;" : "=f"(r) : "f"(x));
    return r;
}
__device__ __forceinline__ float sig_fast(float x) {
    return 0.5f * tanh_fast(0.5f * x) + 0.5f;
}
__device__ __forceinline__ float poll_ld(const float* p) {
    float v;
    asm volatile("ld.volatile.global.f32 %0, [%1];" : "=f"(v) : "l"(p));
    return v;
}
__device__ __forceinline__ void st_vol(float* p, float v) {
    asm volatile("st.volatile.global.f32 [%0], %1;" :: "l"(p), "f"(v));
}
__device__ __forceinline__ unsigned long long pack2(float a, float b) {
    return (unsigned long long)__float_as_uint(a) |
           ((unsigned long long)__float_as_uint(b) << 32);
}
__device__ __forceinline__ float lo2(unsigned long long v) {
    return __uint_as_float((unsigned)(v & 0xffffffffull));
}
__device__ __forceinline__ float hi2(unsigned long long v) {
    return __uint_as_float((unsigned)(v >> 32));
}

// ---------------------------------------------------------------------------
// K1: init h buffers: t==0 -> 0.0f, else canary
// ---------------------------------------------------------------------------
__global__ void init_kernel() {
    int idx = blockIdx.x * 256 + threadIdx.x;
    const int total = 3 * (TT + 1) * HID;
    if (idx < total) {
        int t = (idx / HID) % (TT + 1);
        ((float*)g_hbuf)[idx] = (t == 0) ? 0.0f : __int_as_float(CANARY_I);
    }
}

// ---------------------------------------------------------------------------
// K2: layer-0 input projection (+ both biases), permuted for the pipeline
// ---------------------------------------------------------------------------
__global__ void xg0_kernel(const float* __restrict__ x,
                           const float* __restrict__ w_ih0,
                           const float* __restrict__ b_ih0,
                           const float* __restrict__ b_hh0) {
    __shared__ float xs[8][FIN];
    const int t0 = blockIdx.x * 8;
    const int tid = threadIdx.x;

    for (int i = tid; i < 8 * FIN; i += 256) {
        int tt = i / FIN, f = i % FIN;
        xs[tt][f] = x[((size_t)(BATCH - 1) * TT + (t0 + tt)) * FIN + f];
    }
    __syncthreads();

    const int cta = tid >> 3;
    const int jj  = tid & 7;

    for (int q = 0; q < 4; q++) {
        int grow = q * 256 + tid;
        float w[FIN];
        const float4* wr = (const float4*)(w_ih0 + (size_t)grow * FIN);
        #pragma unroll
        for (int i = 0; i < FIN / 4; i++) {
            float4 v = wr[i];
            w[4 * i] = v.x; w[4 * i + 1] = v.y; w[4 * i + 2] = v.z; w[4 * i + 3] = v.w;
        }
        float bb = b_ih0[grow] + b_hh0[grow];
        #pragma unroll
        for (int tt = 0; tt < 8; tt++) {
            float s = bb;
            #pragma unroll
            for (int f = 0; f < FIN; f++) s += w[f] * xs[tt][f];
            g_xg0[t0 + tt][cta][q * 8 + jj] = s;
        }
    }
}

// ---------------------------------------------------------------------------
// K3: persistent pipelined LSTM.
// 96 CTAs (3 layers x 32), 256 threads (8 warps).
// Warp w owns columns [w*64, w*64+64) of the concatenated [h_in | h_self]
// operand (layers 1,2) or [w*32, w*32+32) of h_self (layer 0), for ALL 32
// gate rows (lane = row). Weights live in REGISTERS (f32x2 pairs).
// Each warp polls exactly the h-words it consumes (NaN-canary data-as-flag),
// stages them in its private harr slice, dots with fma.rn.f32x2, and drops a
// per-row partial into a parity-double-buffered psum. ONE __syncthreads per
// step; warp 7 reduces, activates (tanh.approx), and publishes h.
// ---------------------------------------------------------------------------
__global__ void __launch_bounds__(256, 1)
lstm_pipeline(const float* __restrict__ w_hh0,
              const float* __restrict__ w_ih1, const float* __restrict__ w_hh1,
              const float* __restrict__ b_ih1, const float* __restrict__ b_hh1,
              const float* __restrict__ w_ih2, const float* __restrict__ w_hh2,
              const float* __restrict__ b_ih2, const float* __restrict__ b_hh2) {
    __shared__ float harr[512];
    __shared__ float psum[2][8][32];

    const int layer = blockIdx.x >> 5;
    const int cta   = blockIdx.x & 31;
    const int warp  = threadIdx.x >> 5;
    const int lane  = threadIdx.x & 31;

    const float *wih = nullptr, *whh = nullptr, *bih = nullptr, *bhh = nullptr;
    if (layer == 0)      { whh = w_hh0; }
    else if (layer == 1) { wih = w_ih1; whh = w_hh1; bih = b_ih1; bhh = b_hh1; }
    else                 { wih = w_ih2; whh = w_hh2; bih = b_ih2; bhh = b_hh2; }

    // row owned by this lane
    const int grow = (lane >> 3) * HID + cta * CHUNK + (lane & 7);

    // ---- stage weights into registers (f32x2 pairs) ----
    unsigned long long w2[32];
    if (layer == 0) {
        const int C = warp * 32;
        #pragma unroll
        for (int j = 0; j < 16; j++) {
            float a = whh[(size_t)grow * HID + C + 2 * j];
            float b = whh[(size_t)grow * HID + C + 2 * j + 1];
            w2[j] = pack2(a, b);
        }
    } else {
        const int C = warp * 64;
        #pragma unroll
        for (int j = 0; j < 32; j++) {
            int c = C + 2 * j;
            float a, b;
            if (c < HID) { a = wih[(size_t)grow * HID + c];
                           b = wih[(size_t)grow * HID + c + 1]; }
            else         { a = whh[(size_t)grow * HID + c - HID];
                           b = whh[(size_t)grow * HID + c - HID + 1]; }
            w2[j] = pack2(a, b);
        }
    }

    // reducer-warp per-row bias (layers 1,2; layer 0's bias is inside xg0)
    float biasr = 0.0f;
    if (warp == 7 && layer > 0) biasr = bih[grow] + bhh[grow];

    float creg = 0.0f;   // cell state (warp 7, lanes 0..7)
    int par = 0;

    for (int t = 0; t < TT; t++) {
        // prefetch xg for layer-0 activation (hidden under the poll)
        float xgv = 0.0f;
        if (layer == 0 && warp == 7) xgv = g_xg0[t][cta][lane];

        // ---- poll phase: each warp fetches exactly its 32/64 h-words ----
        if (layer == 0) {
            const float* p = &g_hbuf[0][t][warp * 32 + lane];
            float v;
            do { v = poll_ld(p); } while (__float_as_int(v) == CANARY_I);
            harr[warp * 32 + lane] = v;
        } else if (warp < 4) {
            const float* p0 = &g_hbuf[layer - 1][t + 1][warp * 64 + lane];
            const float* p1 = p0 + 32;
            float v0, v1; int got = 0;
            do {
                if (!(got & 1)) { v0 = poll_ld(p0); if (__float_as_int(v0) != CANARY_I) got |= 1; }
                if (!(got & 2)) { v1 = poll_ld(p1); if (__float_as_int(v1) != CANARY_I) got |= 2; }
            } while (got != 3);
            harr[warp * 64 + lane] = v0;
            harr[warp * 64 + 32 + lane] = v1;
        } else {
            const float* p0 = &g_hbuf[layer][t][(warp - 4) * 64 + lane];
            const float* p1 = p0 + 32;
            float v0, v1; int got = 0;
            do {
                if (!(got & 1)) { v0 = poll_ld(p0); if (__float_as_int(v0) != CANARY_I) got |= 1; }
                if (!(got & 2)) { v1 = poll_ld(p1); if (__float_as_int(v1) != CANARY_I) got |= 2; }
            } while (got != 3);
            harr[warp * 64 + lane] = v0;
            harr[warp * 64 + 32 + lane] = v1;
        }
        __syncwarp(0xffffffffu);

        // ---- dot phase: register weights x broadcast-LDS h ----
        unsigned long long acc0 = 0ull, acc1 = 0ull;
        if (layer == 0) {
            const float* hb = &harr[warp * 32];
            #pragma unroll
            for (int i = 0; i < 8; i++) {
                ulonglong2 hv = *(const ulonglong2*)&hb[4 * i];
                FMA2(acc0, w2[2 * i],     hv.x, acc0);
                FMA2(acc1, w2[2 * i + 1], hv.y, acc1);
            }
        } else {
            const float* hb = &harr[warp * 64];
            #pragma unroll
            for (int i = 0; i < 16; i++) {
                ulonglong2 hv = *(const ulonglong2*)&hb[4 * i];
                FMA2(acc0, w2[2 * i],     hv.x, acc0);
                FMA2(acc1, w2[2 * i + 1], hv.y, acc1);
            }
        }
        float partial = (lo2(acc0) + hi2(acc0)) + (lo2(acc1) + hi2(acc1));
        psum[par][warp][lane] = partial;

        __syncthreads();

        // ---- reducer warp: row-sum, activation, publish ----
        if (warp == 7) {
            float rs = psum[par][0][lane] + psum[par][1][lane]
                     + psum[par][2][lane] + psum[par][3][lane]
                     + psum[par][4][lane] + psum[par][5][lane]
                     + psum[par][6][lane] + psum[par][7][lane];
            rs += (layer == 0) ? xgv : biasr;

            int j = lane & 7;
            float vi = __shfl_sync(0xffffffffu, rs, j);
            float vf = __shfl_sync(0xffffffffu, rs, j + 8);
            float vg = __shfl_sync(0xffffffffu, rs, j + 16);
            float vo = __shfl_sync(0xffffffffu, rs, j + 24);

            float i_ = sig_fast(vi);
            float f_ = sig_fast(vf);
            float g_ = tanh_fast(vg);
            float o_ = sig_fast(vo);
            creg = f_ * creg + i_ * g_;
            float h = o_ * tanh_fast(creg);
            if (lane < CHUNK)
                st_vol(&g_hbuf[layer][t + 1][cta * CHUNK + lane], h);
        }
        par ^= 1;
    }
}

// ---------------------------------------------------------------------------
// K4: classifier GEMM, 512 threads, f32x2 packed FMA.
// ---------------------------------------------------------------------------
__global__ void __launch_bounds__(512)
classify_kernel(const float* __restrict__ wlin,
                const float* __restrict__ blin) {
    __shared__ float hs[8][HID];
    const int t0 = blockIdx.x * 8;
    const int tid = threadIdx.x;

    for (int i = tid; i < 8 * HID; i += 512) {
        int tt = i >> 8, k = i & 255;
        hs[tt][k] = g_hbuf[2][t0 + tt + 1][k];
    }
    __syncthreads();

    for (int spk = tid; spk < NSPK; spk += 512) {
        const unsigned long long* wr =
            (const unsigned long long*)(wlin + (size_t)spk * HID);
        unsigned long long acc[8];
        #pragma unroll
        for (int tt = 0; tt < 8; tt++) acc[tt] = 0ull;

        #pragma unroll 8
        for (int p = 0; p < HID / 2; p += 2) {
            ulonglong2 wv = *(const ulonglong2*)&wr[p];
            #pragma unroll
            for (int tt = 0; tt < 8; tt++) {
                ulonglong2 hv = *(const ulonglong2*)&hs[tt][2 * p];
                FMA2(acc[tt], wv.x, hv.x, acc[tt]);
                FMA2(acc[tt], wv.y, hv.y, acc[tt]);
            }
        }
        float bb = blin[spk];
        #pragma unroll
        for (int tt = 0; tt < 8; tt++) {
            g_logits[(size_t)(t0 + tt) * NSPK + spk] =
                lo2(acc[tt]) + hi2(acc[tt]) + bb;
        }
    }
}

// ---------------------------------------------------------------------------
// K5: row-wise log_softmax
// ---------------------------------------------------------------------------
__global__ void softmax_kernel(float* __restrict__ out) {
    const int t = blockIdx.x;
    const int tid = threadIdx.x;
    __shared__ float red[256];
    const float* row = g_logits + (size_t)t * NSPK;

    float mx = -INFINITY;
    for (int s = tid; s < NSPK; s += 256) mx = fmaxf(mx, row[s]);
    red[tid] = mx; __syncthreads();
    for (int o = 128; o > 0; o >>= 1) {
        if (tid < o) red[tid] = fmaxf(red[tid], red[tid + o]);
        __syncthreads();
    }
    mx = red[0]; __syncthreads();

    float sum = 0.0f;
    for (int s = tid; s < NSPK; s += 256) sum += expf(row[s] - mx);
    red[tid] = sum; __syncthreads();
    for (int o = 128; o > 0; o >>= 1) {
        if (tid < o) red[tid] += red[tid + o];
        __syncthreads();
    }
    float lse = mx + logf(red[0]);

    for (int s = tid; s < NSPK; s += 256) out[(size_t)t * NSPK + s] = row[s] - lse;
}

// ---------------------------------------------------------------------------
extern "C" void kernel_launch(void* const* d_in, const int* in_sizes, int n_in,
                              void* d_out, int out_size) {
    const float* x     = (const float*)d_in[0];
    const float* w_ih0 = (const float*)d_in[1];
    const float* w_hh0 = (const float*)d_in[2];
    const float* b_ih0 = (const float*)d_in[3];
    const float* b_hh0 = (const float*)d_in[4];
    const float* w_ih1 = (const float*)d_in[5];
    const float* w_hh1 = (const float*)d_in[6];
    const float* b_ih1 = (const float*)d_in[7];
    const float* b_hh1 = (const float*)d_in[8];
    const float* w_ih2 = (const float*)d_in[9];
    const float* w_hh2 = (const float*)d_in[10];
    const float* b_ih2 = (const float*)d_in[11];
    const float* b_hh2 = (const float*)d_in[12];
    const float* w_lin = (const float*)d_in[13];
    const float* b_lin = (const float*)d_in[14];
    float* out = (float*)d_out;

    const int init_total = 3 * (TT + 1) * HID;
    init_kernel<<<(init_total + 255) / 256, 256>>>();
    xg0_kernel<<<TT / 8, 256>>>(x, w_ih0, b_ih0, b_hh0);
    lstm_pipeline<<<NCTA, 256>>>(w_hh0,
                                 w_ih1, w_hh1, b_ih1, b_hh1,
                                 w_ih2, w_hh2, b_ih2, b_hh2);
    classify_kernel<<<TT / 8, 512>>>(w_lin, b_lin);
    softmax_kernel<<<TT, 256>>>(out);
}

// round 9
// speedup vs baseline: 1.5433x; 1.1689x over previous
#include <cuda_runtime.h>
#include <cuda_bf16.h>
#include <math.h>
#include <stdint.h>

// Problem dims
#define TT    1024
#define HID   256
#define FIN   40
#define NSPK  1251
#define BATCH 64

// Global-fallback pipeline config
#define G      32
#define CHUNK  8
#define ROWS   32
#define NCTA   (3 * G)

// Cluster pipeline config
#define GC     16       // CTAs per layer-cluster
#define RR     64       // gate rows per CTA
#define CH     16       // h-indices per CTA
#define CW     64       // columns per dot warp
#define NW     8        // dot warps (warp 8 = reducer)
#define THR_CL 288

#define CANARY_I 0x7fb0beef

__device__ float g_hbuf[3][TT + 1][HID];
__device__ float g_xg0[TT][32][32];
__device__ float g_logits[TT * NSPK];

#define FMA2(d, a, b, c) \
    asm("fma.rn.f32x2 %0, %1, %2, %3;" : "=l"(d) : "l"(a), "l"(b), "l"(c))

__device__ __forceinline__ float tanh_fast(float x) {
    float r;
    asm("tanh.approx.f32 %0, %1;" : "=f"(r) : "f"(x));
    return r;
}
__device__ __forceinline__ float sig_fast(float x) {
    return 0.5f * tanh_fast(0.5f * x) + 0.5f;
}
__device__ __forceinline__ float poll_ld(const float* p) {
    float v;
    asm volatile("ld.volatile.global.f32 %0, [%1];" : "=f"(v) : "l"(p) : "memory");
    return v;
}
__device__ __forceinline__ void st_vol(float* p, float v) {
    asm volatile("st.volatile.global.f32 [%0], %1;" :: "l"(p), "f"(v) : "memory");
}
__device__ __forceinline__ float lds_vol(uint32_t a) {
    float v;
    asm volatile("ld.volatile.shared.f32 %0, [%1];" : "=f"(v) : "r"(a) : "memory");
    return v;
}
__device__ __forceinline__ void sts_f32(uint32_t a, float v) {
    asm volatile("st.shared.f32 [%0], %1;" :: "r"(a), "f"(v) : "memory");
}
__device__ __forceinline__ void sts_cluster(uint32_t a, float v) {
    asm volatile("st.shared::cluster.f32 [%0], %1;" :: "r"(a), "f"(v) : "memory");
}
__device__ __forceinline__ uint32_t mapa_u32(uint32_t a, uint32_t r) {
    uint32_t d;
    asm("mapa.shared::cluster.u32 %0, %1, %2;" : "=r"(d) : "r"(a), "r"(r));
    return d;
}
__device__ __forceinline__ unsigned long long pack2(float a, float b) {
    return (unsigned long long)__float_as_uint(a) |
           ((unsigned long long)__float_as_uint(b) << 32);
}
__device__ __forceinline__ float lo2(unsigned long long v) {
    return __uint_as_float((unsigned)(v & 0xffffffffull));
}
__device__ __forceinline__ float hi2(unsigned long long v) {
    return __uint_as_float((unsigned)(v >> 32));
}
#define CLUSTER_BAR() do { \
    asm volatile("barrier.cluster.arrive.aligned;" ::: "memory"); \
    asm volatile("barrier.cluster.wait.aligned;" ::: "memory"); \
} while (0)

// ---------------------------------------------------------------------------
// K1: init global h buffers: t==0 -> 0.0f, else canary
// ---------------------------------------------------------------------------
__global__ void init_kernel() {
    int idx = blockIdx.x * 256 + threadIdx.x;
    const int total = 3 * (TT + 1) * HID;
    if (idx < total) {
        int t = (idx / HID) % (TT + 1);
        ((float*)g_hbuf)[idx] = (t == 0) ? 0.0f : __int_as_float(CANARY_I);
    }
}

// ---------------------------------------------------------------------------
// K2: layer-0 input projection (+ both biases), permuted
// g_xg0[t][(grow&255)>>3][(grow>>8)*8 + (grow&7)]
// ---------------------------------------------------------------------------
__global__ void xg0_kernel(const float* __restrict__ x,
                           const float* __restrict__ w_ih0,
                           const float* __restrict__ b_ih0,
                           const float* __restrict__ b_hh0) {
    __shared__ float xs[8][FIN];
    const int t0 = blockIdx.x * 8;
    const int tid = threadIdx.x;

    for (int i = tid; i < 8 * FIN; i += 256) {
        int tt = i / FIN, f = i % FIN;
        xs[tt][f] = x[((size_t)(BATCH - 1) * TT + (t0 + tt)) * FIN + f];
    }
    __syncthreads();

    const int cta = tid >> 3;
    const int jj  = tid & 7;

    for (int q = 0; q < 4; q++) {
        int grow = q * 256 + tid;
        float w[FIN];
        const float4* wr = (const float4*)(w_ih0 + (size_t)grow * FIN);
        #pragma unroll
        for (int i = 0; i < FIN / 4; i++) {
            float4 v = wr[i];
            w[4 * i] = v.x; w[4 * i + 1] = v.y; w[4 * i + 2] = v.z; w[4 * i + 3] = v.w;
        }
        float bb = b_ih0[grow] + b_hh0[grow];
        #pragma unroll
        for (int tt = 0; tt < 8; tt++) {
            float s = bb;
            #pragma unroll
            for (int f = 0; f < FIN; f++) s += w[f] * xs[tt][f];
            g_xg0[t0 + tt][cta][q * 8 + jj] = s;
        }
    }
}

// ---------------------------------------------------------------------------
// K3a: CLUSTER pipeline. 48 CTAs = 3 clusters of 16 (one per layer).
// 288 threads: warps 0-7 dot, warp 8 reducer.
// ONE __syncthreads per step (psum ordering); inter-CTA h via DSMEM
// NaN-canary data-as-flag. All warps stay alive through the whole loop.
// ---------------------------------------------------------------------------
__global__ void __launch_bounds__(THR_CL, 1)
lstm_cluster(const float* __restrict__ w_hh0,
             const float* __restrict__ w_ih1, const float* __restrict__ w_hh1,
             const float* __restrict__ b_ih1, const float* __restrict__ b_hh1,
             const float* __restrict__ w_ih2, const float* __restrict__ w_hh2,
             const float* __restrict__ b_ih2, const float* __restrict__ b_hh2) {
    __shared__ __align__(16) float self_h[2][256];
    __shared__ __align__(16) float in_stage[256];
    __shared__ __align__(16) float psum[2][RR][NW];

    const int layer = blockIdx.x >> 4;
    const int cta   = blockIdx.x & 15;
    const int warp  = threadIdx.x >> 5;
    const int lane  = threadIdx.x & 31;
    const float CAN = __int_as_float(CANARY_I);

    // init smem: slot0 = h(0) = 0, slot1 = canary
    for (int i = threadIdx.x; i < 256; i += THR_CL) {
        self_h[0][i] = 0.0f;
        self_h[1][i] = CAN;
    }
    __syncthreads();
    CLUSTER_BAR();

    const float *wih = nullptr, *whh = nullptr, *bih = nullptr, *bhh = nullptr;
    if (layer == 0)      { whh = w_hh0; }
    else if (layer == 1) { wih = w_ih1; whh = w_hh1; bih = b_ih1; bhh = b_hh1; }
    else                 { wih = w_ih2; whh = w_hh2; bih = b_ih2; bhh = b_hh2; }

    if (warp < NW) {
        // ---------------- dot warps ----------------
        const bool self_side = (warp >= 4);
        const bool active = !(layer == 0 && !self_side);

        const int cs = self_side ? (warp - 4) * CW : warp * CW;
        const float* Wsrc = self_side ? whh : wih;

        unsigned long long w2[64];
        if (active) {
            #pragma unroll
            for (int k = 0; k < 2; k++) {
                int grow = ((lane >> 4) + 2 * k) * 256 + cta * CH + (lane & 15);
                const float* wr = Wsrc + (size_t)grow * HID + cs;
                #pragma unroll
                for (int j = 0; j < 32; j++)
                    w2[32 * k + j] = pack2(wr[2 * j], wr[2 * j + 1]);
            }
        }

        uint32_t sa0[2], sa1[2], pso[2];
        #pragma unroll
        for (int p = 0; p < 2; p++) {
            sa0[p] = (uint32_t)__cvta_generic_to_shared(&self_h[p][cs + lane]);
            sa1[p] = sa0[p] + 32 * 4;
            pso[p] = (uint32_t)__cvta_generic_to_shared(&psum[p][lane][warp]);
        }

        for (int t = 0; t < TT; t++) {
            const int par = t & 1;
            if (active) {
                const float* hb;
                if (self_side) {
                    float v0, v1; int got = 0;
                    do {
                        if (!(got & 1)) { v0 = lds_vol(sa0[par]); if (__float_as_int(v0) != CANARY_I) got |= 1; }
                        if (!(got & 2)) { v1 = lds_vol(sa1[par]); if (__float_as_int(v1) != CANARY_I) got |= 2; }
                    } while (got != 3);
                    __syncwarp();
                    hb = &self_h[par][cs];
                } else {
                    const float* p0 = &g_hbuf[layer - 1][t + 1][cs + lane];
                    const float* p1 = p0 + 32;
                    float v0, v1; int got = 0;
                    do {
                        if (!(got & 1)) { v0 = poll_ld(p0); if (__float_as_int(v0) != CANARY_I) got |= 1; }
                        if (!(got & 2)) { v1 = poll_ld(p1); if (__float_as_int(v1) != CANARY_I) got |= 2; }
                    } while (got != 3);
                    in_stage[cs + lane] = v0;
                    in_stage[cs + lane + 32] = v1;
                    __syncwarp();
                    hb = &in_stage[cs];
                }

                unsigned long long a00 = 0, a01 = 0, a10 = 0, a11 = 0;
                #pragma unroll
                for (int jj = 0; jj < 16; jj++) {
                    ulonglong2 hv = *(const ulonglong2*)(hb + 4 * jj);
                    FMA2(a00, w2[2 * jj],      hv.x, a00);
                    FMA2(a01, w2[2 * jj + 1],  hv.y, a01);
                    FMA2(a10, w2[32 + 2 * jj], hv.x, a10);
                    FMA2(a11, w2[33 + 2 * jj], hv.y, a11);
                }
                if (self_side) {               // reset consumed slot to canary
                    __syncwarp();
                    sts_f32(sa0[par], CAN);
                    sts_f32(sa1[par], CAN);
                }
                float pa = (lo2(a00) + hi2(a00)) + (lo2(a01) + hi2(a01));
                float pb = (lo2(a10) + hi2(a10)) + (lo2(a11) + hi2(a11));
                sts_f32(pso[par], pa);
                sts_f32(pso[par] + 32 * NW * 4, pb);
            }
            __syncthreads();   // B(t): psum(t) visible; reducer consumed psum(t-1)
        }
        CLUSTER_BAR();
        return;
    }

    // ---------------- reducer warp (warp 8) ----------------
    {
        int grow0 = (lane >> 4) * 256 + cta * CH + (lane & 15);
        int grow1 = grow0 + 2 * 256;
        float b0 = 0.0f, b1 = 0.0f;
        int xi0 = 0, xi1 = 0;
        if (layer > 0) {
            b0 = bih[grow0] + bhh[grow0];
            b1 = bih[grow1] + bhh[grow1];
        } else {
            int r0 = grow0 & 255, r1 = grow1 & 255;
            xi0 = ((r0 >> 3) << 5) + ((grow0 >> 8) << 3) + (r0 & 7);
            xi1 = ((r1 >> 3) << 5) + ((grow1 >> 8) << 3) + (r1 & 7);
        }

        const int j = lane & 15;
        uint32_t hpub[2];
        #pragma unroll
        for (int p = 0; p < 2; p++)
            hpub[p] = (uint32_t)__cvta_generic_to_shared(&self_h[p][cta * CH + j]);
        const int pbase = (lane >> 4) * 8;

        float creg = 0.0f;

        for (int t = 0; t < TT; t++) {
            const int par = t & 1;
            float xga = 0.0f, xgb = 0.0f;
            if (layer == 0) {
                const float* xf = (const float*)g_xg0 + (size_t)t * 1024;
                xga = __ldg(xf + xi0);
                xgb = __ldg(xf + xi1);
            }

            __syncthreads();   // B(t): dot warps' psum(t) now visible

            float rs0, rs1;
            if (layer == 0) {
                float4 A1 = *(const float4*)&psum[par][lane][4];
                float4 B1 = *(const float4*)&psum[par][lane + 32][4];
                rs0 = (A1.x + A1.y) + (A1.z + A1.w) + xga;
                rs1 = (B1.x + B1.y) + (B1.z + B1.w) + xgb;
            } else {
                float4 A0 = *(const float4*)&psum[par][lane][0];
                float4 A1 = *(const float4*)&psum[par][lane][4];
                float4 B0 = *(const float4*)&psum[par][lane + 32][0];
                float4 B1 = *(const float4*)&psum[par][lane + 32][4];
                rs0 = ((A0.x + A0.y) + (A0.z + A0.w)) + ((A1.x + A1.y) + (A1.z + A1.w)) + b0;
                rs1 = ((B0.x + B0.y) + (B0.z + B0.w)) + ((B1.x + B1.y) + (B1.z + B1.w)) + b1;
            }

            // gates: i = row j, f = row j+16 (rs0); g = row 32+j, o = row 48+j (rs1)
            float vi = __shfl_sync(0xffffffffu, rs0, j);
            float vf = __shfl_sync(0xffffffffu, rs0, j + 16);
            float vg = __shfl_sync(0xffffffffu, rs1, j);
            float vo = __shfl_sync(0xffffffffu, rs1, j + 16);

            float i_ = sig_fast(vi);
            float f_ = sig_fast(vf);
            float g_ = tanh_fast(vg);
            float o_ = sig_fast(vo);
            creg = f_ * creg + i_ * g_;
            float h = o_ * tanh_fast(creg);

            // publish h(t+1): DSMEM to all 16 peers (half-warp splits the peer
            // set), then L2 for the layer above / classifier
            uint32_t la = hpub[par ^ 1];
            #pragma unroll
            for (int i = 0; i < 8; i++)
                sts_cluster(mapa_u32(la, pbase + i), h);
            if (lane < 16)
                st_vol(&g_hbuf[layer][t + 1][cta * CH + j], h);
        }
        CLUSTER_BAR();
    }
}

// ---------------------------------------------------------------------------
// K3b: FALLBACK global-L2 pipeline (proven R2 kernel, 1120us)
// ---------------------------------------------------------------------------
__global__ void __launch_bounds__(256, 1)
lstm_pipeline(const float* __restrict__ w_hh0,
              const float* __restrict__ w_ih1, const float* __restrict__ w_hh1,
              const float* __restrict__ b_ih1, const float* __restrict__ b_hh1,
              const float* __restrict__ w_ih2, const float* __restrict__ w_hh2,
              const float* __restrict__ b_ih2, const float* __restrict__ b_hh2) {
    __shared__ float harr[512];
    __shared__ float psum[2][8][32];

    const int layer = blockIdx.x >> 5;
    const int cta   = blockIdx.x & 31;
    const int warp  = threadIdx.x >> 5;
    const int lane  = threadIdx.x & 31;

    const float *wih = nullptr, *whh = nullptr, *bih = nullptr, *bhh = nullptr;
    if (layer == 0)      { whh = w_hh0; }
    else if (layer == 1) { wih = w_ih1; whh = w_hh1; bih = b_ih1; bhh = b_hh1; }
    else                 { wih = w_ih2; whh = w_hh2; bih = b_ih2; bhh = b_hh2; }

    const int grow = (lane >> 3) * HID + cta * CHUNK + (lane & 7);

    unsigned long long w2[32];
    if (layer == 0) {
        const int C = warp * 32;
        #pragma unroll
        for (int j = 0; j < 16; j++)
            w2[j] = pack2(whh[(size_t)grow * HID + C + 2 * j],
                          whh[(size_t)grow * HID + C + 2 * j + 1]);
    } else {
        const int C = warp * 64;
        #pragma unroll
        for (int j = 0; j < 32; j++) {
            int c = C + 2 * j;
            float a, b;
            if (c < HID) { a = wih[(size_t)grow * HID + c];
                           b = wih[(size_t)grow * HID + c + 1]; }
            else         { a = whh[(size_t)grow * HID + c - HID];
                           b = whh[(size_t)grow * HID + c - HID + 1]; }
            w2[j] = pack2(a, b);
        }
    }

    float biasr = 0.0f;
    if (warp == 7 && layer > 0) biasr = bih[grow] + bhh[grow];

    float creg = 0.0f;
    int par = 0;

    for (int t = 0; t < TT; t++) {
        float xgv = 0.0f;
        if (layer == 0 && warp == 7) xgv = g_xg0[t][cta][lane];

        if (layer == 0) {
            const float* p = &g_hbuf[0][t][warp * 32 + lane];
            float v;
            do { v = poll_ld(p); } while (__float_as_int(v) == CANARY_I);
            harr[warp * 32 + lane] = v;
        } else if (warp < 4) {
            const float* p0 = &g_hbuf[layer - 1][t + 1][warp * 64 + lane];
            const float* p1 = p0 + 32;
            float v0, v1; int got = 0;
            do {
                if (!(got & 1)) { v0 = poll_ld(p0); if (__float_as_int(v0) != CANARY_I) got |= 1; }
                if (!(got & 2)) { v1 = poll_ld(p1); if (__float_as_int(v1) != CANARY_I) got |= 2; }
            } while (got != 3);
            harr[warp * 64 + lane] = v0;
            harr[warp * 64 + 32 + lane] = v1;
        } else {
            const float* p0 = &g_hbuf[layer][t][(warp - 4) * 64 + lane];
            const float* p1 = p0 + 32;
            float v0, v1; int got = 0;
            do {
                if (!(got & 1)) { v0 = poll_ld(p0); if (__float_as_int(v0) != CANARY_I) got |= 1; }
                if (!(got & 2)) { v1 = poll_ld(p1); if (__float_as_int(v1) != CANARY_I) got |= 2; }
            } while (got != 3);
            harr[warp * 64 + lane] = v0;
            harr[warp * 64 + 32 + lane] = v1;
        }
        __syncwarp(0xffffffffu);

        unsigned long long acc0 = 0ull, acc1 = 0ull;
        if (layer == 0) {
            const float* hb = &harr[warp * 32];
            #pragma unroll
            for (int i = 0; i < 8; i++) {
                ulonglong2 hv = *(const ulonglong2*)&hb[4 * i];
                FMA2(acc0, w2[2 * i],     hv.x, acc0);
                FMA2(acc1, w2[2 * i + 1], hv.y, acc1);
            }
        } else {
            const float* hb = &harr[warp * 64];
            #pragma unroll
            for (int i = 0; i < 16; i++) {
                ulonglong2 hv = *(const ulonglong2*)&hb[4 * i];
                FMA2(acc0, w2[2 * i],     hv.x, acc0);
                FMA2(acc1, w2[2 * i + 1], hv.y, acc1);
            }
        }
        float partial = (lo2(acc0) + hi2(acc0)) + (lo2(acc1) + hi2(acc1));
        psum[par][warp][lane] = partial;

        __syncthreads();

        if (warp == 7) {
            float rs = psum[par][0][lane] + psum[par][1][lane]
                     + psum[par][2][lane] + psum[par][3][lane]
                     + psum[par][4][lane] + psum[par][5][lane]
                     + psum[par][6][lane] + psum[par][7][lane];
            rs += (layer == 0) ? xgv : biasr;

            int j = lane & 7;
            float vi = __shfl_sync(0xffffffffu, rs, j);
            float vf = __shfl_sync(0xffffffffu, rs, j + 8);
            float vg = __shfl_sync(0xffffffffu, rs, j + 16);
            float vo = __shfl_sync(0xffffffffu, rs, j + 24);

            float i_ = sig_fast(vi);
            float f_ = sig_fast(vf);
            float g_ = tanh_fast(vg);
            float o_ = sig_fast(vo);
            creg = f_ * creg + i_ * g_;
            float h = o_ * tanh_fast(creg);
            if (lane < CHUNK)
                st_vol(&g_hbuf[layer][t + 1][cta * CHUNK + lane], h);
        }
        par ^= 1;
    }
}

// ---------------------------------------------------------------------------
// K4: classifier GEMM, grid (128,3) x 512 threads
// ---------------------------------------------------------------------------
__global__ void __launch_bounds__(512)
classify_kernel(const float* __restrict__ wlin,
                const float* __restrict__ blin) {
    __shared__ float hs[8][HID];
    const int t0 = blockIdx.x * 8;
    const int tid = threadIdx.x;

    for (int i = tid; i < 8 * HID; i += 512) {
        int tt = i >> 8, k = i & 255;
        hs[tt][k] = g_hbuf[2][t0 + tt + 1][k];
    }
    __syncthreads();

    int spk = blockIdx.y * 512 + tid;
    if (spk < NSPK) {
        const unsigned long long* wr =
            (const unsigned long long*)(wlin + (size_t)spk * HID);
        unsigned long long acc[8];
        #pragma unroll
        for (int tt = 0; tt < 8; tt++) acc[tt] = 0ull;

        #pragma unroll 8
        for (int p = 0; p < HID / 2; p += 2) {
            ulonglong2 wv = *(const ulonglong2*)&wr[p];
            #pragma unroll
            for (int tt = 0; tt < 8; tt++) {
                ulonglong2 hv = *(const ulonglong2*)&hs[tt][2 * p];
                FMA2(acc[tt], wv.x, hv.x, acc[tt]);
                FMA2(acc[tt], wv.y, hv.y, acc[tt]);
            }
        }
        float bb = blin[spk];
        #pragma unroll
        for (int tt = 0; tt < 8; tt++) {
            g_logits[(size_t)(t0 + tt) * NSPK + spk] =
                lo2(acc[tt]) + hi2(acc[tt]) + bb;
        }
    }
}

// ---------------------------------------------------------------------------
// K5: row-wise log_softmax
// ---------------------------------------------------------------------------
__global__ void softmax_kernel(float* __restrict__ out) {
    const int t = blockIdx.x;
    const int tid = threadIdx.x;
    __shared__ float red[256];
    const float* row = g_logits + (size_t)t * NSPK;

    float mx = -INFINITY;
    for (int s = tid; s < NSPK; s += 256) mx = fmaxf(mx, row[s]);
    red[tid] = mx; __syncthreads();
    for (int o = 128; o > 0; o >>= 1) {
        if (tid < o) red[tid] = fmaxf(red[tid], red[tid + o]);
        __syncthreads();
    }
    mx = red[0]; __syncthreads();

    float sum = 0.0f;
    for (int s = tid; s < NSPK; s += 256) sum += expf(row[s] - mx);
    red[tid] = sum; __syncthreads();
    for (int o = 128; o > 0; o >>= 1) {
        if (tid < o) red[tid] += red[tid + o];
        __syncthreads();
    }
    float lse = mx + logf(red[0]);

    for (int s = tid; s < NSPK; s += 256) out[(size_t)t * NSPK + s] = row[s] - lse;
}

// ---------------------------------------------------------------------------
extern "C" void kernel_launch(void* const* d_in, const int* in_sizes, int n_in,
                              void* d_out, int out_size) {
    const float* x     = (const float*)d_in[0];
    const float* w_ih0 = (const float*)d_in[1];
    const float* w_hh0 = (const float*)d_in[2];
    const float* b_ih0 = (const float*)d_in[3];
    const float* b_hh0 = (const float*)d_in[4];
    const float* w_ih1 = (const float*)d_in[5];
    const float* w_hh1 = (const float*)d_in[6];
    const float* b_ih1 = (const float*)d_in[7];
    const float* b_hh1 = (const float*)d_in[8];
    const float* w_ih2 = (const float*)d_in[9];
    const float* w_hh2 = (const float*)d_in[10];
    const float* b_ih2 = (const float*)d_in[11];
    const float* b_hh2 = (const float*)d_in[12];
    const float* w_lin = (const float*)d_in[13];
    const float* b_lin = (const float*)d_in[14];
    float* out = (float*)d_out;

    const int init_total = 3 * (TT + 1) * HID;
    init_kernel<<<(init_total + 255) / 256, 256>>>();
    xg0_kernel<<<TT / 8, 256>>>(x, w_ih0, b_ih0, b_hh0);

    // Prefer 16-CTA-cluster DSMEM pipeline; fall back to global-L2 version.
    cudaFuncSetAttribute(lstm_cluster,
                         cudaFuncAttributeNonPortableClusterSizeAllowed, 1);
    cudaLaunchConfig_t cfg = {};
    cfg.gridDim  = dim3(3 * GC, 1, 1);
    cfg.blockDim = dim3(THR_CL, 1, 1);
    cfg.dynamicSmemBytes = 0;
    cudaLaunchAttribute at[1];
    at[0].id = cudaLaunchAttributeClusterDimension;
    at[0].val.clusterDim.x = GC;
    at[0].val.clusterDim.y = 1;
    at[0].val.clusterDim.z = 1;
    cfg.attrs = at;
    cfg.numAttrs = 1;

    int maxc = 0;
    cudaError_t qe = cudaOccupancyMaxPotentialClusterSize(&maxc, lstm_cluster, &cfg);

    bool launched = false;
    if (qe == cudaSuccess && maxc >= GC) {
        cudaError_t le = cudaLaunchKernelEx(&cfg, lstm_cluster, w_hh0,
                                            w_ih1, w_hh1, b_ih1, b_hh1,
                                            w_ih2, w_hh2, b_ih2, b_hh2);
        launched = (le == cudaSuccess);
        if (!launched) (void)cudaGetLastError();   // clear sticky error
    }
    if (!launched) {
        lstm_pipeline<<<NCTA, 256>>>(w_hh0,
                                     w_ih1, w_hh1, b_ih1, b_hh1,
                                     w_ih2, w_hh2, b_ih2, b_hh2);
    }

    classify_kernel<<<dim3(TT / 8, 3), 512>>>(w_lin, b_lin);
    softmax_kernel<<<TT, 256>>>(out);
}